// round 10
// baseline (speedup 1.0000x reference)
#include <cuda_runtime.h>

#define NN 50000
#define NE 800000
#define ET (NE + NN)
#define NC 64
#define NCHUNK ((NN + 1023) / 1024)
#define NBIN 64

// ---------------------------------------------------------------------------
// Static device scratch (allocation-free rule).
// ---------------------------------------------------------------------------
__device__ float g_hA[NN * NC];
__device__ float g_hB[NN * NC];
__device__ int   g_csrc[ET + 16];     // CSR: src BYTE offsets (src*256), +16 pad
__device__ int   g_rank[ET];          // per-edge rank within its dst (from hist)
__device__ int   g_rowptr[NN + 1];
__device__ int   g_cnt[NN];           // zero at entry (reset by layer2 epilogue)
__device__ int   g_agg[NCHUNK];       // decoupled-lookback state
__device__ int   g_inc[NCHUNK];
__device__ int   g_flag[NCHUNK];      // zeroed by k_hist each call
__device__ int   g_dcnt[NBIN];        // degree histogram (zeroed by k_hist)
__device__ int   g_doff[NBIN];
__device__ int   g_dcur[NBIN];
__device__ int   g_perm[NN];          // nodes sorted by degree bin

// ---------------------------------------------------------------------------
// CSR build (R8-exact: this configuration measured fastest)
// ---------------------------------------------------------------------------
__global__ void k_hist(const int* __restrict__ ei) {
    int e = blockIdx.x * blockDim.x + threadIdx.x;
    if (e < NCHUNK) g_flag[e] = 0;
    if (e < NBIN) g_dcnt[e] = 0;
    if (e >= ET) return;
    int dst = (e < NE) ? ei[NE + e] : (e - NE);
    g_rank[e] = atomicAdd(&g_cnt[dst], 1);    // rank = arrival order within dst
}

__global__ void __launch_bounds__(1024) k_scan() {
    __shared__ int s[1024];
    __shared__ int s_off;
    int c = blockIdx.x, tid = threadIdx.x;
    int i = c * 1024 + tid;
    int v = (i < NN) ? g_cnt[i] : 0;
    if (i < NN) atomicAdd(&g_dcnt[v < NBIN ? v : NBIN - 1], 1);   // degree bins
    s[tid] = v;
    __syncthreads();
    for (int off = 1; off < 1024; off <<= 1) {
        int t = (tid >= off) ? s[tid - off] : 0;
        __syncthreads();
        s[tid] += t;
        __syncthreads();
    }
    if (tid == 0) {
        int total = s[1023];
        g_agg[c] = total;
        __threadfence();
        atomicExch(&g_flag[c], 1);
        int off = 0;
        for (int j = c - 1; j >= 0;) {
            int f;
            do { f = atomicAdd(&g_flag[j], 0); } while (f == 0);
            if (f == 2) { off += atomicAdd(&g_inc[j], 0); break; }
            off += atomicAdd(&g_agg[j], 0);
            j--;
        }
        g_inc[c] = off + total;
        __threadfence();
        atomicExch(&g_flag[c], 2);
        s_off = off;
    }
    __syncthreads();
    if (i < NN) g_rowptr[i] = s_off + s[tid] - v;
    if (c == 0 && tid == 0) g_rowptr[NN] = ET;
}

__global__ void k_dscan() {       // 64 threads, 1 block: bin offsets
    __shared__ int s[NBIN];
    int t = threadIdx.x;
    int v = g_dcnt[t];
    s[t] = v;
    __syncthreads();
    for (int off = 1; off < NBIN; off <<= 1) {
        int u = (t >= off) ? s[t - off] : 0;
        __syncthreads();
        s[t] += u;
        __syncthreads();
    }
    g_doff[t] = s[t] - v;
    g_dcur[t] = 0;
}

__global__ void k_scatter(const int* __restrict__ ei) {
    int e = blockIdx.x * blockDim.x + threadIdx.x;
    if (e < NN) {                 // build degree-binned permutation
        int deg = g_rowptr[e + 1] - g_rowptr[e];
        int b = deg < NBIN ? deg : NBIN - 1;
        int p = atomicAdd(&g_dcur[b], 1);
        g_perm[g_doff[b] + p] = e;
    }
    if (e >= ET) return;
    int src, dst;
    if (e < NE) { src = ei[e]; dst = ei[NE + e]; }
    else        { src = dst = e - NE; }
    g_csrc[g_rowptr[dst] + g_rank[e]] = src << 8;   // byte offset (256 B/row)
}

// ---------------------------------------------------------------------------
// Fused GAT layer, 4-edge iterations. 16 lanes own one dst node (degree-
// sorted via g_perm). Plain softmax (logit sigma ~1; exp(d)/sum identical to
// max-shifted form). Per 4 edges (A,B,C,D x heads 0,1 = 8 values):
//   one packed butterfly (15 shfl, lane bits 3/2/1 select edge-pair/edge/head),
//   ONE exp per lane, 8 broadcasts. Software-pipelined row loads.
// ---------------------------------------------------------------------------
__device__ __forceinline__ float lrelu(float v) { return fmaxf(v, 0.2f * v); }

template<int LAYER>
__global__ void __launch_bounds__(256) k_layer(
    const float* __restrict__ h, float* __restrict__ hnext, float* __restrict__ acc,
    const float* __restrict__ attl, const float* __restrict__ biasl)
{
    const unsigned FM = 0xffffffffu;
    int sub  = threadIdx.x >> 4;
    int lane = threadIdx.x & 15;
    int gi   = blockIdx.x * 16 + sub;          // grid*16 == NN exactly
    int node = g_perm[gi];                     // uniform across subgroup

    int start = g_rowptr[node];
    int deg   = g_rowptr[node + 1] - start;    // >= 1 (self loop)

    const char* hb = (const char*)h;
    int lane16 = lane * 16;
    float4 xd = *(const float4*)(hb + (size_t)node * 256 + lane16);
    float4 a0 = ((const float4*)attl)[lane];
    float4 a1 = ((const float4*)(attl + NC))[lane];

    float sacc = 0.f;
    float4 c0 = make_float4(0.f, 0.f, 0.f, 0.f);
    float4 c1 = make_float4(0.f, 0.f, 0.f, 0.f);

    const int* cs = g_csrc + start;   // over-reads (up to +9+16 pad) are safe:
                                      // they hit later CSR entries or zero pad
    int j0 = cs[0], j1 = cs[1];
    float4 xA = *(const float4*)(hb + j0 + lane16);
    float4 xB = *(const float4*)(hb + j1 + lane16);
    int j2 = cs[2], j3 = cs[3], j4 = cs[4], j5 = cs[5];

    for (int e = 0; e < deg; e += 4) {
        float4 xC = *(const float4*)(hb + j2 + lane16);
        float4 xD = *(const float4*)(hb + j3 + lane16);

        // logits for A, B (covers the C/D loads)
        float vx, vy, vz, vw;
        vx = lrelu(xd.x + xA.x); vy = lrelu(xd.y + xA.y);
        vz = lrelu(xd.z + xA.z); vw = lrelu(xd.w + xA.w);
        float dA0 = vx * a0.x + vy * a0.y + vz * a0.z + vw * a0.w;
        float dA1 = vx * a1.x + vy * a1.y + vz * a1.z + vw * a1.w;
        vx = lrelu(xd.x + xB.x); vy = lrelu(xd.y + xB.y);
        vz = lrelu(xd.z + xB.z); vw = lrelu(xd.w + xB.w);
        float dB0 = vx * a0.x + vy * a0.y + vz * a0.z + vw * a0.w;
        float dB1 = vx * a1.x + vy * a1.y + vz * a1.z + vw * a1.w;

        // prefetch next iteration's A,B rows and indices
        float4 nA = *(const float4*)(hb + j4 + lane16);
        float4 nB = *(const float4*)(hb + j5 + lane16);
        j2 = cs[e + 6]; j3 = cs[e + 7]; j4 = cs[e + 8]; j5 = cs[e + 9];

        // logits for C, D
        vx = lrelu(xd.x + xC.x); vy = lrelu(xd.y + xC.y);
        vz = lrelu(xd.z + xC.z); vw = lrelu(xd.w + xC.w);
        float dC0 = vx * a0.x + vy * a0.y + vz * a0.z + vw * a0.w;
        float dC1 = vx * a1.x + vy * a1.y + vz * a1.z + vw * a1.w;
        vx = lrelu(xd.x + xD.x); vy = lrelu(xd.y + xD.y);
        vz = lrelu(xd.z + xD.z); vw = lrelu(xd.w + xD.w);
        float dD0 = vx * a0.x + vy * a0.y + vz * a0.z + vw * a0.w;
        float dD1 = vx * a1.x + vy * a1.y + vz * a1.z + vw * a1.w;

        // packed butterfly: 8 values -> 1 per lane (bits: b3=pair, b2=edge, b1=head)
        dA0 += __shfl_xor_sync(FM, dA0, 8, 16);
        dA1 += __shfl_xor_sync(FM, dA1, 8, 16);
        dB0 += __shfl_xor_sync(FM, dB0, 8, 16);
        dB1 += __shfl_xor_sync(FM, dB1, 8, 16);
        dC0 += __shfl_xor_sync(FM, dC0, 8, 16);
        dC1 += __shfl_xor_sync(FM, dC1, 8, 16);
        dD0 += __shfl_xor_sync(FM, dD0, 8, 16);
        dD1 += __shfl_xor_sync(FM, dD1, 8, 16);
        float u0 = (lane & 8) ? dC0 : dA0;
        float u1 = (lane & 8) ? dC1 : dA1;
        float u2 = (lane & 8) ? dD0 : dB0;
        float u3 = (lane & 8) ? dD1 : dB1;
        u0 += __shfl_xor_sync(FM, u0, 4, 16);
        u1 += __shfl_xor_sync(FM, u1, 4, 16);
        u2 += __shfl_xor_sync(FM, u2, 4, 16);
        u3 += __shfl_xor_sync(FM, u3, 4, 16);
        float v0 = (lane & 4) ? u2 : u0;       // b2: A/C vs B/D
        float v1 = (lane & 4) ? u3 : u1;
        v0 += __shfl_xor_sync(FM, v0, 2, 16);
        v1 += __shfl_xor_sync(FM, v1, 2, 16);
        float w = (lane & 2) ? v1 : v0;        // b1: head
        w += __shfl_xor_sync(FM, w, 1, 16);
        float ew = __expf(w);                  // one exp per lane, 4 edges

        // lane L holds value (edge = (L>>2)&3 mapped A,B,C,D; head = (L>>1)&1)
        // valid-edge mask for the denominator; bit0 dedups the 2x replication
        int eo = (lane >> 2) & 3;              // 0:A(C-pair via b3 packed) ...
        // mapping check: b3=0,b2=0 -> A ; b3=0,b2=1 -> B ; b3=1,b2=0 -> C ; b3=1,b2=1 -> D
        // eo = b2 + 2*b3 = ((lane>>2)&1) + ((lane>>3)&1)*2
        eo = ((lane >> 2) & 1) + ((lane >> 3) & 1) * 2;
        bool svalid = (e + eo < deg) && !(lane & 1);
        sacc += svalid ? ew : 0.f;

        float pA0 = __shfl_sync(FM, ew, 0, 16);
        float pA1 = __shfl_sync(FM, ew, 2, 16);
        float pB0 = __shfl_sync(FM, ew, 4, 16);
        float pB1 = __shfl_sync(FM, ew, 6, 16);
        float pC0 = __shfl_sync(FM, ew, 8, 16);
        float pC1 = __shfl_sync(FM, ew, 10, 16);
        float pD0 = __shfl_sync(FM, ew, 12, 16);
        float pD1 = __shfl_sync(FM, ew, 14, 16);
        if (e + 1 >= deg) { pB0 = 0.f; pB1 = 0.f; }
        if (e + 2 >= deg) { pC0 = 0.f; pC1 = 0.f; }
        if (e + 3 >= deg) { pD0 = 0.f; pD1 = 0.f; }

        c0.x += xA.x * pA0 + xB.x * pB0 + xC.x * pC0 + xD.x * pD0;
        c0.y += xA.y * pA0 + xB.y * pB0 + xC.y * pC0 + xD.y * pD0;
        c0.z += xA.z * pA0 + xB.z * pB0 + xC.z * pC0 + xD.z * pD0;
        c0.w += xA.w * pA0 + xB.w * pB0 + xC.w * pC0 + xD.w * pD0;
        c1.x += xA.x * pA1 + xB.x * pB1 + xC.x * pC1 + xD.x * pD1;
        c1.y += xA.y * pA1 + xB.y * pB1 + xC.y * pC1 + xD.y * pD1;
        c1.z += xA.z * pA1 + xB.z * pB1 + xC.z * pC1 + xD.z * pD1;
        c1.w += xA.w * pA1 + xB.w * pB1 + xC.w * pC1 + xD.w * pD1;

        xA = nA; xB = nB;
    }

    // finalize denominators: combine lanes over bits 3,2,0; head lives on bit1
    float t = sacc + __shfl_xor_sync(FM, sacc, 8, 16);
    t += __shfl_xor_sync(FM, t, 4, 16);
    t += __shfl_xor_sync(FM, t, 1, 16);
    float other = __shfl_xor_sync(FM, t, 2, 16);
    float s0 = (lane & 2) ? other : t;
    float s1 = (lane & 2) ? t : other;

    float i0 = 0.5f / (s0 + 1e-16f), i1 = 0.5f / (s1 + 1e-16f);
    float4 b = ((const float4*)biasl)[lane];
    float4 av;
    av.x = c0.x * i0 + c1.x * i1 + b.x;
    av.y = c0.y * i0 + c1.y * i1 + b.y;
    av.z = c0.z * i0 + c1.z * i1 + b.z;
    av.w = c0.w * i0 + c1.w * i1 + b.w;

    float4* ap = (float4*)acc + node * 16 + lane;
    if (LAYER == 0) {
        ((float4*)hnext)[node * 16 + lane] = av;
        float4 o; o.x = xd.x + av.x; o.y = xd.y + av.y; o.z = xd.z + av.z; o.w = xd.w + av.w;
        *ap = o;                               // acc = x + h1
    } else if (LAYER == 1) {
        ((float4*)hnext)[node * 16 + lane] = av;
        float4 o = *ap;
        o.x += av.x; o.y += av.y; o.z += av.z; o.w += av.w;
        *ap = o;
    } else {
        float4 o = *ap;                        // acc = (acc + h3) / 4
        o.x = (o.x + av.x) * 0.25f; o.y = (o.y + av.y) * 0.25f;
        o.z = (o.z + av.z) * 0.25f; o.w = (o.w + av.w) * 0.25f;
        *ap = o;
        int tt = blockIdx.x * blockDim.x + threadIdx.x;
        if (tt < NN) g_cnt[tt] = 0;            // reset histogram for next replay
    }
}

// ---------------------------------------------------------------------------
// Launch
// ---------------------------------------------------------------------------
extern "C" void kernel_launch(void* const* d_in, const int* in_sizes, int n_in,
                              void* d_out, int out_size) {
    const float* x    = (const float*)d_in[0];
    const int*   ei   = (const int*)d_in[1];
    const float* att  = (const float*)d_in[2];
    const float* bias = (const float*)d_in[3];
    float*       out  = (float*)d_out;

    float *hA, *hB;
    cudaGetSymbolAddress((void**)&hA, g_hA);
    cudaGetSymbolAddress((void**)&hB, g_hB);

    const int gridE = (ET + 255) / 256;
    const int gridL = NN / 16;                 // 3125, exact

    k_hist<<<gridE, 256>>>(ei);
    k_scan<<<NCHUNK, 1024>>>();
    k_dscan<<<1, NBIN>>>();
    k_scatter<<<gridE, 256>>>(ei);

    k_layer<0><<<gridL, 256>>>(x,  hA, out, att + 0 * 2 * NC, bias + 0 * NC);
    k_layer<1><<<gridL, 256>>>(hA, hB, out, att + 1 * 2 * NC, bias + 1 * NC);
    k_layer<2><<<gridL, 256>>>(hB, hA, out, att + 2 * 2 * NC, bias + 2 * NC);
}

// round 11
// speedup vs baseline: 1.1582x; 1.1582x over previous
#include <cuda_runtime.h>

#define NN 50000
#define NE 800000
#define ET (NE + NN)
#define NC 64
#define NCHUNK ((NN + 1023) / 1024)
#define NBIN 64

// ---------------------------------------------------------------------------
// Static device scratch (allocation-free rule).
// ---------------------------------------------------------------------------
__device__ float g_hA[NN * NC];
__device__ float g_hB[NN * NC];
__device__ int   g_csrc[ET + 16];     // CSR: src BYTE offsets (src*256), +16 pad
__device__ int   g_rank[ET];          // per-edge rank within its dst (from hist)
__device__ int   g_rowptr[NN + 1];
__device__ int   g_cnt[NN];           // zero at entry (reset by layer2 epilogue)
__device__ int   g_agg[NCHUNK];       // decoupled-lookback state
__device__ int   g_inc[NCHUNK];
__device__ int   g_flag[NCHUNK];      // zeroed by k_hist each call
__device__ int   g_dcnt[NBIN];        // degree histogram (zeroed by k_hist)
__device__ int   g_doff[NBIN];
__device__ int   g_dcur[NBIN];
__device__ int   g_perm[NN];          // nodes sorted by degree bin (DESCENDING)

// ---------------------------------------------------------------------------
// CSR build (R8-exact kernels; only k_dscan's offset order changed)
// ---------------------------------------------------------------------------
__global__ void k_hist(const int* __restrict__ ei) {
    int e = blockIdx.x * blockDim.x + threadIdx.x;
    if (e < NCHUNK) g_flag[e] = 0;
    if (e < NBIN) g_dcnt[e] = 0;
    if (e >= ET) return;
    int dst = (e < NE) ? ei[NE + e] : (e - NE);
    g_rank[e] = atomicAdd(&g_cnt[dst], 1);    // rank = arrival order within dst
}

__global__ void __launch_bounds__(1024) k_scan() {
    __shared__ int s[1024];
    __shared__ int s_off;
    int c = blockIdx.x, tid = threadIdx.x;
    int i = c * 1024 + tid;
    int v = (i < NN) ? g_cnt[i] : 0;
    if (i < NN) atomicAdd(&g_dcnt[v < NBIN ? v : NBIN - 1], 1);   // degree bins
    s[tid] = v;
    __syncthreads();
    for (int off = 1; off < 1024; off <<= 1) {
        int t = (tid >= off) ? s[tid - off] : 0;
        __syncthreads();
        s[tid] += t;
        __syncthreads();
    }
    if (tid == 0) {
        int total = s[1023];
        g_agg[c] = total;
        __threadfence();
        atomicExch(&g_flag[c], 1);
        int off = 0;
        for (int j = c - 1; j >= 0;) {
            int f;
            do { f = atomicAdd(&g_flag[j], 0); } while (f == 0);
            if (f == 2) { off += atomicAdd(&g_inc[j], 0); break; }
            off += atomicAdd(&g_agg[j], 0);
            j--;
        }
        g_inc[c] = off + total;
        __threadfence();
        atomicExch(&g_flag[c], 2);
        s_off = off;
    }
    __syncthreads();
    if (i < NN) g_rowptr[i] = s_off + s[tid] - v;
    if (c == 0 && tid == 0) g_rowptr[NN] = ET;
}

// Bin offsets in DESCENDING degree order: heavy nodes occupy the front of
// g_perm so the layer grid's first wave takes the longest blocks and the
// tail wave the lightest (shrinks per-layer straggler tail).
__global__ void k_dscan() {       // 64 threads, 1 block
    __shared__ int s[NBIN];
    int t = threadIdx.x;
    int rt = NBIN - 1 - t;        // reversed position
    int v = g_dcnt[rt];           // count of bin rt
    s[t] = v;
    __syncthreads();
    for (int off = 1; off < NBIN; off <<= 1) {
        int u = (t >= off) ? s[t - off] : 0;
        __syncthreads();
        s[t] += u;
        __syncthreads();
    }
    g_doff[rt] = s[t] - v;        // exclusive prefix in reversed order
    g_dcur[rt] = 0;
}

__global__ void k_scatter(const int* __restrict__ ei) {
    int e = blockIdx.x * blockDim.x + threadIdx.x;
    if (e < NN) {                 // build degree-binned permutation
        int deg = g_rowptr[e + 1] - g_rowptr[e];
        int b = deg < NBIN ? deg : NBIN - 1;
        int p = atomicAdd(&g_dcur[b], 1);
        g_perm[g_doff[b] + p] = e;
    }
    if (e >= ET) return;
    int src, dst;
    if (e < NE) { src = ei[e]; dst = ei[NE + e]; }
    else        { src = dst = e - NE; }
    g_csrc[g_rowptr[dst] + g_rank[e]] = src << 8;   // byte offset (256 B/row)
}

// ---------------------------------------------------------------------------
// Fused GAT layer (R8-exact core). 16 lanes own one dst node, degree-sorted
// via g_perm. Plain softmax (logit sigma ~1, no overflow risk; identical to
// shifted form). Per 2 edges: scalar logits, packed 12-shfl butterfly,
// ONE exp per lane, 4 broadcasts. Guard-free prefetch via padded g_csrc.
// ---------------------------------------------------------------------------
__device__ __forceinline__ float lrelu(float v) { return fmaxf(v, 0.2f * v); }

template<int LAYER>
__global__ void __launch_bounds__(256) k_layer(
    const float* __restrict__ h, float* __restrict__ hnext, float* __restrict__ acc,
    const float* __restrict__ attl, const float* __restrict__ biasl)
{
    const unsigned FM = 0xffffffffu;
    int sub  = threadIdx.x >> 4;
    int lane = threadIdx.x & 15;
    int gi   = blockIdx.x * 16 + sub;          // grid*16 == NN exactly
    int node = g_perm[gi];                     // uniform across subgroup

    int start = g_rowptr[node];
    int deg   = g_rowptr[node + 1] - start;    // >= 1 (self loop)

    const char* hb = (const char*)h;
    int lane16 = lane * 16;
    float4 xd = *(const float4*)(hb + (size_t)node * 256 + lane16);
    float4 a0 = ((const float4*)attl)[lane];
    float4 a1 = ((const float4*)(attl + NC))[lane];

    float sacc = 0.f;
    float4 c0 = make_float4(0.f, 0.f, 0.f, 0.f);
    float4 c1 = make_float4(0.f, 0.f, 0.f, 0.f);

    const int* cs = g_csrc + start;            // over-reads hit pad/neighbors
    int j0 = cs[0], j1 = cs[1];
    float4 xA = *(const float4*)(hb + j0 + lane16);
    float4 xB = *(const float4*)(hb + j1 + lane16);
    int j2 = cs[2], j3 = cs[3];

    for (int e = 0; e < deg; e += 2) {
        float4 nA = *(const float4*)(hb + j2 + lane16);   // unconditional prefetch
        float4 nB = *(const float4*)(hb + j3 + lane16);
        j2 = cs[e + 4]; j3 = cs[e + 5];

        float vx, vy, vz, vw;
        vx = lrelu(xd.x + xA.x); vy = lrelu(xd.y + xA.y);
        vz = lrelu(xd.z + xA.z); vw = lrelu(xd.w + xA.w);
        float dA0 = vx * a0.x + vy * a0.y + vz * a0.z + vw * a0.w;
        float dA1 = vx * a1.x + vy * a1.y + vz * a1.z + vw * a1.w;
        vx = lrelu(xd.x + xB.x); vy = lrelu(xd.y + xB.y);
        vz = lrelu(xd.z + xB.z); vw = lrelu(xd.w + xB.w);
        float dB0 = vx * a0.x + vy * a0.y + vz * a0.z + vw * a0.w;
        float dB1 = vx * a1.x + vy * a1.y + vz * a1.z + vw * a1.w;

        // packed butterfly: 4 sums -> 1 per lane, one exp per lane
        dA0 += __shfl_xor_sync(FM, dA0, 8, 16);
        dA1 += __shfl_xor_sync(FM, dA1, 8, 16);
        dB0 += __shfl_xor_sync(FM, dB0, 8, 16);
        dB1 += __shfl_xor_sync(FM, dB1, 8, 16);
        float u0 = (lane & 8) ? dB0 : dA0;     // bit3 selects edge
        float u1 = (lane & 8) ? dB1 : dA1;
        u0 += __shfl_xor_sync(FM, u0, 4, 16);
        u1 += __shfl_xor_sync(FM, u1, 4, 16);
        float w = (lane & 4) ? u1 : u0;        // bit2 selects head
        w += __shfl_xor_sync(FM, w, 2, 16);
        w += __shfl_xor_sync(FM, w, 1, 16);
        float ew = __expf(w);

        bool bval = (e + 1 < deg);
        sacc += (bval || lane < 8) ? ew : 0.f;

        float pA0 = __shfl_sync(FM, ew, 0, 16);
        float pA1 = __shfl_sync(FM, ew, 4, 16);
        float pB0 = __shfl_sync(FM, ew, 8, 16);
        float pB1 = __shfl_sync(FM, ew, 12, 16);
        if (!bval) { pB0 = 0.f; pB1 = 0.f; }

        c0.x += xA.x * pA0 + xB.x * pB0;  c0.y += xA.y * pA0 + xB.y * pB0;
        c0.z += xA.z * pA0 + xB.z * pB0;  c0.w += xA.w * pA0 + xB.w * pB0;
        c1.x += xA.x * pA1 + xB.x * pB1;  c1.y += xA.y * pA1 + xB.y * pB1;
        c1.z += xA.z * pA1 + xB.z * pB1;  c1.w += xA.w * pA1 + xB.w * pB1;

        xA = nA; xB = nB;
    }

    // finalize denominators (lane-partial layout: bit3 = edge, bit2 = head)
    float sO = sacc + __shfl_xor_sync(FM, sacc, 8, 16);
    float sX = __shfl_xor_sync(FM, sO, 4, 16);
    float s0 = (lane & 4) ? sX : sO;
    float s1 = (lane & 4) ? sO : sX;

    float i0 = 0.5f / (s0 + 1e-16f), i1 = 0.5f / (s1 + 1e-16f);
    float4 b = ((const float4*)biasl)[lane];
    float4 av;
    av.x = c0.x * i0 + c1.x * i1 + b.x;
    av.y = c0.y * i0 + c1.y * i1 + b.y;
    av.z = c0.z * i0 + c1.z * i1 + b.z;
    av.w = c0.w * i0 + c1.w * i1 + b.w;

    float4* ap = (float4*)acc + node * 16 + lane;
    if (LAYER == 0) {
        ((float4*)hnext)[node * 16 + lane] = av;
        float4 o; o.x = xd.x + av.x; o.y = xd.y + av.y; o.z = xd.z + av.z; o.w = xd.w + av.w;
        *ap = o;                               // acc = x + h1
    } else if (LAYER == 1) {
        ((float4*)hnext)[node * 16 + lane] = av;
        float4 o = *ap;
        o.x += av.x; o.y += av.y; o.z += av.z; o.w += av.w;
        *ap = o;
    } else {
        float4 o = *ap;                        // acc = (acc + h3) / 4
        o.x = (o.x + av.x) * 0.25f; o.y = (o.y + av.y) * 0.25f;
        o.z = (o.z + av.z) * 0.25f; o.w = (o.w + av.w) * 0.25f;
        *ap = o;
        int t = blockIdx.x * blockDim.x + threadIdx.x;
        if (t < NN) g_cnt[t] = 0;              // reset histogram for next replay
    }
}

// ---------------------------------------------------------------------------
// Launch
// ---------------------------------------------------------------------------
extern "C" void kernel_launch(void* const* d_in, const int* in_sizes, int n_in,
                              void* d_out, int out_size) {
    const float* x    = (const float*)d_in[0];
    const int*   ei   = (const int*)d_in[1];
    const float* att  = (const float*)d_in[2];
    const float* bias = (const float*)d_in[3];
    float*       out  = (float*)d_out;

    float *hA, *hB;
    cudaGetSymbolAddress((void**)&hA, g_hA);
    cudaGetSymbolAddress((void**)&hB, g_hB);

    const int gridE = (ET + 255) / 256;
    const int gridL = NN / 16;                 // 3125, exact

    k_hist<<<gridE, 256>>>(ei);
    k_scan<<<NCHUNK, 1024>>>();
    k_dscan<<<1, NBIN>>>();
    k_scatter<<<gridE, 256>>>(ei);

    k_layer<0><<<gridL, 256>>>(x,  hA, out, att + 0 * 2 * NC, bias + 0 * NC);
    k_layer<1><<<gridL, 256>>>(hA, hB, out, att + 1 * 2 * NC, bias + 1 * NC);
    k_layer<2><<<gridL, 256>>>(hB, hA, out, att + 2 * 2 * NC, bias + 2 * NC);
}